// round 8
// baseline (speedup 1.0000x reference)
#include <cuda_runtime.h>
#include <cuda_fp16.h>
#include <math.h>
#include <stdint.h>

#define T_TOK 1024
#define HDIM  2048
#define NEXP  64
#define IDIM  768
#define TOPK  8

// ---------------- device scratch ----------------
__device__ int    g_count[NEXP];
__device__ int    g_entry[NEXP * T_TOK];           // token*8 + slot
__device__ float  g_wt   [NEXP * T_TOK];
__device__ __half g_act  [T_TOK * TOPK * IDIM];    // fp16 silu(g)*u*w, gathered
__device__ __half g_x16  [T_TOK * HDIM];           // fp16 copy of hidden_states

// ---------------- helpers ----------------
__device__ __forceinline__ uint32_t smem_u32(const void* p) {
    uint32_t a;
    asm("{ .reg .u64 t; cvta.to.shared.u64 t, %1; cvt.u32.u64 %0, t; }" : "=r"(a) : "l"(p));
    return a;
}
__device__ __forceinline__ void sts128(uint32_t a, uint32_t x, uint32_t y, uint32_t z, uint32_t w) {
    asm volatile("st.shared.v4.b32 [%0], {%1,%2,%3,%4};" :: "r"(a), "r"(x), "r"(y), "r"(z), "r"(w));
}
__device__ __forceinline__ void ldsm4(uint32_t& r0, uint32_t& r1, uint32_t& r2, uint32_t& r3, uint32_t a) {
    asm volatile("ldmatrix.sync.aligned.m8n8.x4.shared.b16 {%0,%1,%2,%3}, [%4];"
                 : "=r"(r0), "=r"(r1), "=r"(r2), "=r"(r3) : "r"(a));
}
__device__ __forceinline__ void ldsm4t(uint32_t& r0, uint32_t& r1, uint32_t& r2, uint32_t& r3, uint32_t a) {
    asm volatile("ldmatrix.sync.aligned.m8n8.x4.trans.shared.b16 {%0,%1,%2,%3}, [%4];"
                 : "=r"(r0), "=r"(r1), "=r"(r2), "=r"(r3) : "r"(a));
}
__device__ __forceinline__ void mma_h(float& c0, float& c1, float& c2, float& c3,
                                      uint32_t a0, uint32_t a1, uint32_t a2, uint32_t a3,
                                      uint32_t b0, uint32_t b1) {
    asm volatile("mma.sync.aligned.m16n8k16.row.col.f32.f16.f16.f32 "
                 "{%0,%1,%2,%3},{%4,%5,%6,%7},{%8,%9},{%0,%1,%2,%3};"
                 : "+f"(c0), "+f"(c1), "+f"(c2), "+f"(c3)
                 : "r"(a0), "r"(a1), "r"(a2), "r"(a3), "r"(b0), "r"(b1));
}
__device__ __forceinline__ void cvt2h(float4 f, uint32_t& h0, uint32_t& h1) {
    __half2 a = __floats2half2_rn(f.x, f.y);
    __half2 b = __floats2half2_rn(f.z, f.w);
    h0 = *(uint32_t*)&a; h1 = *(uint32_t*)&b;
}

// named-barrier producer/consumer primitives (count = 384 threads)
#define BARS(id) asm volatile("bar.sync %0, 384;"   :: "r"(id) : "memory")
#define BARA(id) asm volatile("bar.arrive %0, 384;" :: "r"(id) : "memory")
#define FENCE()  asm volatile("membar.cta;" ::: "memory")

// smem geometry (fp16 elems):
//   A tile 128x32, row stride 40 elems (80B, ldsm conflict-free)
//   B64 tile 32x64,  row stride 72 elems (144B, conflict-free)
//   B128 tile 32x128, row stride 136 elems (272B, conflict-free)
#define A_BYTES    10240   // 128*40*2
#define B1_BYTES   4608    // 32*72*2
#define B128_BYTES 8704    // 32*272
#define NSTAGE 6

// ---------------- kernel 0: reset counters ----------------
__global__ void zero_counts_kernel() {
    if (threadIdx.x < NEXP) g_count[threadIdx.x] = 0;
}

// ---------------- kernel 0b: x -> fp16 ----------------
__global__ __launch_bounds__(256)
void xcvt_kernel(const float* __restrict__ x) {
    int i = (blockIdx.x * 256 + threadIdx.x) * 8;
    float4 f0 = *(const float4*)(x + i);
    float4 f1 = *(const float4*)(x + i + 4);
    uint4 v;
    cvt2h(f0, v.x, v.y);
    cvt2h(f1, v.z, v.w);
    *(uint4*)(g_x16 + i) = v;
}

// ---------------- kernel 1: router GEMM + top-8 + bucket scatter ----------------
__global__ __launch_bounds__(256)
void router_kernel(const float* __restrict__ x, const float* __restrict__ gw) {
    __shared__ float As[16][17];
    __shared__ float Bs[16][68];
    __shared__ float Ls[16][68];

    const int t0  = blockIdx.x * 16;
    const int tid = threadIdx.x;
    const int tx  = tid & 15;
    const int ty  = tid >> 4;

    const int am = tid >> 4, ak = tid & 15;
    const int be = tid & 63, bk4 = (tid >> 6) * 4;

    float acc[4] = {0.f, 0.f, 0.f, 0.f};

    for (int k0 = 0; k0 < HDIM; k0 += 16) {
        As[ak][am] = x[(size_t)(t0 + am) * HDIM + k0 + ak];
        float4 bv = *(const float4*)(gw + (size_t)be * HDIM + k0 + bk4);
        Bs[bk4 + 0][be] = bv.x; Bs[bk4 + 1][be] = bv.y;
        Bs[bk4 + 2][be] = bv.z; Bs[bk4 + 3][be] = bv.w;
        __syncthreads();
#pragma unroll
        for (int kk = 0; kk < 16; kk++) {
            float a = As[kk][ty];
#pragma unroll
            for (int j = 0; j < 4; j++) acc[j] += a * Bs[kk][tx * 4 + j];
        }
        __syncthreads();
    }

#pragma unroll
    for (int j = 0; j < 4; j++) Ls[ty][tx * 4 + j] = acc[j];
    __syncthreads();

    if (tid < 16) {
        int   sel[TOPK];
        float sv [TOPK];
        unsigned long long mask = 0ull;
#pragma unroll
        for (int k = 0; k < TOPK; k++) {
            float best = -1e30f;
            int   be_  = 0;
            for (int e = 0; e < NEXP; e++) {
                if ((mask >> e) & 1ull) continue;
                float v = Ls[tid][e];
                if (v > best) { best = v; be_ = e; }
            }
            mask |= (1ull << be_);
            sel[k] = be_;
            sv[k]  = best;
        }
        float mx = sv[0];
        float s  = 0.f;
#pragma unroll
        for (int k = 0; k < TOPK; k++) { sv[k] = expf(sv[k] - mx); s += sv[k]; }
        float inv = 1.f / s;
#pragma unroll
        for (int k = 0; k < TOPK; k++) {
            int e   = sel[k];
            int pos = atomicAdd(&g_count[e], 1);
            g_entry[e * T_TOK + pos] = (t0 + tid) * TOPK + k;
            g_wt   [e * T_TOK + pos] = sv[k] * inv;
        }
    }
}

// ---------------- kernel 2: gate+up, warp-specialized producer/consumer ----------------
// 8 consumer warps (tiling as R7: BM=128, BN=64, warp 32x32 for g AND u),
// 4 producer warps feeding a 6-deep smem ring.
#define GU_STAGE (A_BYTES + 2 * B1_BYTES)            // 19456
#define GU_SMEM  (1024 + NSTAGE * GU_STAGE)          // 117760

__global__ __launch_bounds__(384, 1)
void gateup_mma(const float* __restrict__ wg,
                const float* __restrict__ wu) {
    extern __shared__ char smem[];
    const int e   = blockIdx.z;
    const int cnt = g_count[e];
    const int m0  = blockIdx.y * 128;
    if (m0 >= cnt) return;
    const int n0  = blockIdx.x * 64;
    const int tid  = threadIdx.x;
    const int wid  = tid >> 5;
    const int lane = tid & 31;

    const uint32_t sb = smem_u32(smem);
    int*   sEnt = (int*)smem;
    float* sW   = (float*)(smem + 512);

    if (tid < 128) {
        int mi = m0 + tid;
        if (mi < cnt) { sEnt[tid] = g_entry[e * T_TOK + mi]; sW[tid] = g_wt[e * T_TOK + mi]; }
        else          { sEnt[tid] = -1;                      sW[tid] = 0.f; }
    }
    __syncthreads();

    const int C = HDIM / 32;   // 64 chunks

    if (tid >= 256) {
        // ---------------- producers (4 warps) ----------------
        const int ptid = tid - 256;                  // 0..127
        const int prow = ptid;                       // A row
        const int pent = sEnt[prow];
        const __half* pa = g_x16 + (size_t)(pent >= 0 ? (pent >> 3) : 0) * HDIM;
        const bool pav = (pent >= 0);
        const uint32_t aoff = (uint32_t)(prow * 80);

        const int btile = ptid >> 6;                 // 0=gate, 1=up
        const int bt = ptid & 63;
        const int pbrow = bt >> 1, pbc = (bt & 1) * 32;
        const float* pw = (btile ? wu : wg) + (size_t)e * HDIM * IDIM + n0 + pbc;
        const uint32_t boff = (uint32_t)(A_BYTES + btile * B1_BYTES + pbrow * 144 + pbc * 2);

        for (int c = 0; c < C; c++) {
            const int slot = c % NSTAGE;
            const uint32_t base = sb + 1024 + slot * GU_STAGE;
            if (c >= NSTAGE) BARS(7 + slot);
            // A tile row (fp16 copy)
            if (pav) {
                const __half* ap = pa + c * 32;
                uint4 v0 = *(const uint4*)(ap);
                uint4 v1 = *(const uint4*)(ap + 8);
                uint4 v2 = *(const uint4*)(ap + 16);
                uint4 v3 = *(const uint4*)(ap + 24);
                sts128(base + aoff,      v0.x, v0.y, v0.z, v0.w);
                sts128(base + aoff + 16, v1.x, v1.y, v1.z, v1.w);
                sts128(base + aoff + 32, v2.x, v2.y, v2.z, v2.w);
                sts128(base + aoff + 48, v3.x, v3.y, v3.z, v3.w);
            } else if (c < NSTAGE) {
                sts128(base + aoff,      0u, 0u, 0u, 0u);
                sts128(base + aoff + 16, 0u, 0u, 0u, 0u);
                sts128(base + aoff + 32, 0u, 0u, 0u, 0u);
                sts128(base + aoff + 48, 0u, 0u, 0u, 0u);
            }
            // B tile (gate or up): 32 fp32 -> fp16
            {
                const float* src = pw + (size_t)(c * 32 + pbrow) * IDIM;
                float4 f0 = *(const float4*)(src);
                float4 f1 = *(const float4*)(src + 4);
                float4 f2 = *(const float4*)(src + 8);
                float4 f3 = *(const float4*)(src + 12);
                float4 f4 = *(const float4*)(src + 16);
                float4 f5 = *(const float4*)(src + 20);
                float4 f6 = *(const float4*)(src + 24);
                float4 f7 = *(const float4*)(src + 28);
                uint32_t h0, h1, h2, h3;
                cvt2h(f0, h0, h1); cvt2h(f1, h2, h3);
                sts128(base + boff, h0, h1, h2, h3);
                cvt2h(f2, h0, h1); cvt2h(f3, h2, h3);
                sts128(base + boff + 16, h0, h1, h2, h3);
                cvt2h(f4, h0, h1); cvt2h(f5, h2, h3);
                sts128(base + boff + 32, h0, h1, h2, h3);
                cvt2h(f6, h0, h1); cvt2h(f7, h2, h3);
                sts128(base + boff + 48, h0, h1, h2, h3);
            }
            FENCE();
            BARA(1 + slot);
        }
        return;
    }

    // ---------------- consumers (8 warps) ----------------
    const int wm = wid >> 1, wn = wid & 1;
    const bool strip_active = (m0 + wm * 32) < cnt;

    float accg[2][4][4], accu[2][4][4];
#pragma unroll
    for (int i = 0; i < 2; i++)
#pragma unroll
        for (int j = 0; j < 4; j++)
#pragma unroll
            for (int q = 0; q < 4; q++) { accg[i][j][q] = 0.f; accu[i][j][q] = 0.f; }

    for (int c = 0; c < C; c++) {
        const int slot = c % NSTAGE;
        const uint32_t base = sb + 1024 + slot * GU_STAGE;
        BARS(1 + slot);
        if (strip_active) {
            const uint32_t Ah = base;
            const uint32_t Bg = base + A_BYTES, Bu = Bg + B1_BYTES;
#pragma unroll
            for (int kk = 0; kk < 2; kk++) {
                uint32_t ah[2][4];
                const uint32_t acol = (kk * 16 + (lane >> 4) * 8) * 2;
#pragma unroll
                for (int i = 0; i < 2; i++) {
                    uint32_t ra = (wm * 32 + i * 16 + (lane & 15)) * 80 + acol;
                    ldsm4(ah[i][0], ah[i][1], ah[i][2], ah[i][3], Ah + ra);
                }
                const uint32_t brow_ = kk * 16 + ((lane >> 3) & 1) * 8 + (lane & 7);
#pragma unroll
                for (int hf = 0; hf < 2; hf++) {
                    const uint32_t rb = brow_ * 144 + (wn * 32 + hf * 16 + (lane >> 4) * 8) * 2;
                    uint32_t g0, g1, g2, g3;
                    ldsm4t(g0, g1, g2, g3, Bg + rb);
#pragma unroll
                    for (int i = 0; i < 2; i++) {
                        float* c0 = accg[i][hf * 2 + 0];
                        float* c1 = accg[i][hf * 2 + 1];
                        mma_h(c0[0], c0[1], c0[2], c0[3], ah[i][0], ah[i][1], ah[i][2], ah[i][3], g0, g1);
                        mma_h(c1[0], c1[1], c1[2], c1[3], ah[i][0], ah[i][1], ah[i][2], ah[i][3], g2, g3);
                    }
                    uint32_t u0, u1, u2, u3;
                    ldsm4t(u0, u1, u2, u3, Bu + rb);
#pragma unroll
                    for (int i = 0; i < 2; i++) {
                        float* c0 = accu[i][hf * 2 + 0];
                        float* c1 = accu[i][hf * 2 + 1];
                        mma_h(c0[0], c0[1], c0[2], c0[3], ah[i][0], ah[i][1], ah[i][2], ah[i][3], u0, u1);
                        mma_h(c1[0], c1[1], c1[2], c1[3], ah[i][0], ah[i][1], ah[i][2], ah[i][3], u2, u3);
                    }
                }
            }
        }
        BARA(7 + slot);
    }

    // epilogue: silu(g)*u*w -> fp16 plane
    if (strip_active) {
#pragma unroll
        for (int i = 0; i < 2; i++)
#pragma unroll
            for (int nt = 0; nt < 4; nt++) {
                const int r    = wm * 32 + i * 16 + (lane >> 2);
                const int cof  = n0 + wn * 32 + nt * 8 + (lane & 3) * 2;
#pragma unroll
                for (int half_ = 0; half_ < 2; half_++) {
                    const int rr  = r + half_ * 8;
                    const int ent = sEnt[rr];
                    if (ent >= 0) {
                        const float w = sW[rr];
                        float g0 = accg[i][nt][half_ * 2 + 0], g1 = accg[i][nt][half_ * 2 + 1];
                        float u0 = accu[i][nt][half_ * 2 + 0], u1 = accu[i][nt][half_ * 2 + 1];
                        float v0 = g0 / (1.f + expf(-g0)) * u0 * w;
                        float v1 = g1 / (1.f + expf(-g1)) * u1 * w;
                        *(__half2*)(g_act + (size_t)ent * IDIM + cof) =
                            __floats2half2_rn(v0, v1);
                    }
                }
            }
    }
}

// ---------------- kernel 3: down GEMM, warp-specialized, BN=128 ----------------
#define DN_STAGE (A_BYTES + B128_BYTES)              // 18944
#define DN_SMEM  (1024 + NSTAGE * DN_STAGE)          // 114688

__global__ __launch_bounds__(384, 1)
void down_mma(const float* __restrict__ wd, float* __restrict__ out) {
    extern __shared__ char smem[];
    const int e   = blockIdx.z;
    const int cnt = g_count[e];
    const int m0  = blockIdx.y * 128;
    if (m0 >= cnt) return;
    const int n0  = blockIdx.x * 128;
    const int tid  = threadIdx.x;
    const int wid  = tid >> 5;
    const int lane = tid & 31;

    const uint32_t sb = smem_u32(smem);
    int* sEnt = (int*)smem;

    if (tid < 128) {
        int mi = m0 + tid;
        sEnt[tid] = (mi < cnt) ? g_entry[e * T_TOK + mi] : -1;
    }
    __syncthreads();

    const int C = IDIM / 32;   // 24 chunks

    if (tid >= 256) {
        // ---------------- producers ----------------
        const int ptid = tid - 256;
        const int prow = ptid;
        const int pent = sEnt[prow];
        const __half* pa = g_act + (size_t)(pent >= 0 ? pent : 0) * IDIM;
        const bool pav = (pent >= 0);
        const uint32_t aoff = (uint32_t)(prow * 80);

        const int pbrow = ptid >> 2, pbc = (ptid & 3) * 32;
        const float* pw = wd + (size_t)e * IDIM * HDIM + n0 + pbc;
        const uint32_t boff = (uint32_t)(A_BYTES + pbrow * 272 + pbc * 2);

        for (int c = 0; c < C; c++) {
            const int slot = c % NSTAGE;
            const uint32_t base = sb + 1024 + slot * DN_STAGE;
            if (c >= NSTAGE) BARS(7 + slot);
            if (pav) {
                const __half* ap = pa + c * 32;
                uint4 v0 = *(const uint4*)(ap);
                uint4 v1 = *(const uint4*)(ap + 8);
                uint4 v2 = *(const uint4*)(ap + 16);
                uint4 v3 = *(const uint4*)(ap + 24);
                sts128(base + aoff,      v0.x, v0.y, v0.z, v0.w);
                sts128(base + aoff + 16, v1.x, v1.y, v1.z, v1.w);
                sts128(base + aoff + 32, v2.x, v2.y, v2.z, v2.w);
                sts128(base + aoff + 48, v3.x, v3.y, v3.z, v3.w);
            } else if (c < NSTAGE) {
                sts128(base + aoff,      0u, 0u, 0u, 0u);
                sts128(base + aoff + 16, 0u, 0u, 0u, 0u);
                sts128(base + aoff + 32, 0u, 0u, 0u, 0u);
                sts128(base + aoff + 48, 0u, 0u, 0u, 0u);
            }
            {
                const float* src = pw + (size_t)(c * 32 + pbrow) * HDIM;
                float4 f0 = *(const float4*)(src);
                float4 f1 = *(const float4*)(src + 4);
                float4 f2 = *(const float4*)(src + 8);
                float4 f3 = *(const float4*)(src + 12);
                float4 f4 = *(const float4*)(src + 16);
                float4 f5 = *(const float4*)(src + 20);
                float4 f6 = *(const float4*)(src + 24);
                float4 f7 = *(const float4*)(src + 28);
                uint32_t h0, h1, h2, h3;
                cvt2h(f0, h0, h1); cvt2h(f1, h2, h3);
                sts128(base + boff, h0, h1, h2, h3);
                cvt2h(f2, h0, h1); cvt2h(f3, h2, h3);
                sts128(base + boff + 16, h0, h1, h2, h3);
                cvt2h(f4, h0, h1); cvt2h(f5, h2, h3);
                sts128(base + boff + 32, h0, h1, h2, h3);
                cvt2h(f6, h0, h1); cvt2h(f7, h2, h3);
                sts128(base + boff + 48, h0, h1, h2, h3);
            }
            FENCE();
            BARA(1 + slot);
        }
        return;
    }

    // ---------------- consumers ----------------
    const int wm = wid >> 1, wn = wid & 1;
    const bool strip_active = (m0 + wm * 32) < cnt;

    float acc[2][8][4];
#pragma unroll
    for (int i = 0; i < 2; i++)
#pragma unroll
        for (int j = 0; j < 8; j++)
#pragma unroll
            for (int q = 0; q < 4; q++) acc[i][j][q] = 0.f;

    for (int c = 0; c < C; c++) {
        const int slot = c % NSTAGE;
        const uint32_t base = sb + 1024 + slot * DN_STAGE;
        BARS(1 + slot);
        if (strip_active) {
            const uint32_t Ah = base;
            const uint32_t Bh = base + A_BYTES;
#pragma unroll
            for (int kk = 0; kk < 2; kk++) {
                uint32_t ah[2][4];
                const uint32_t acol = (kk * 16 + (lane >> 4) * 8) * 2;
#pragma unroll
                for (int i = 0; i < 2; i++) {
                    uint32_t ra = (wm * 32 + i * 16 + (lane & 15)) * 80 + acol;
                    ldsm4(ah[i][0], ah[i][1], ah[i][2], ah[i][3], Ah + ra);
                }
                const uint32_t brow_ = kk * 16 + ((lane >> 3) & 1) * 8 + (lane & 7);
#pragma unroll
                for (int hf = 0; hf < 4; hf++) {
                    const uint32_t rb = brow_ * 272 + (wn * 64 + hf * 16 + (lane >> 4) * 8) * 2;
                    uint32_t b0, b1, b2, b3;
                    ldsm4t(b0, b1, b2, b3, Bh + rb);
#pragma unroll
                    for (int i = 0; i < 2; i++) {
                        float* c0 = acc[i][hf * 2 + 0];
                        float* c1 = acc[i][hf * 2 + 1];
                        mma_h(c0[0], c0[1], c0[2], c0[3], ah[i][0], ah[i][1], ah[i][2], ah[i][3], b0, b1);
                        mma_h(c1[0], c1[1], c1[2], c1[3], ah[i][0], ah[i][1], ah[i][2], ah[i][3], b2, b3);
                    }
                }
            }
        }
        BARA(7 + slot);
    }

    if (strip_active) {
#pragma unroll
        for (int i = 0; i < 2; i++)
#pragma unroll
            for (int nt = 0; nt < 8; nt++) {
                const int r   = wm * 32 + i * 16 + (lane >> 2);
                const int cof = n0 + wn * 64 + nt * 8 + (lane & 3) * 2;
#pragma unroll
                for (int half_ = 0; half_ < 2; half_++) {
                    const int rr  = r + half_ * 8;
                    const int ent = sEnt[rr];
                    if (ent >= 0) {
                        float* dst = out + (size_t)(ent >> 3) * HDIM + cof;
                        atomicAdd(dst,     acc[i][nt][half_ * 2 + 0]);
                        atomicAdd(dst + 1, acc[i][nt][half_ * 2 + 1]);
                    }
                }
            }
    }
}

// ---------------- launch ----------------
extern "C" void kernel_launch(void* const* d_in, const int* in_sizes, int n_in,
                              void* d_out, int out_size) {
    const float* x  = (const float*)d_in[0];
    const float* gw = (const float*)d_in[1];
    const float* wg = (const float*)d_in[2];
    const float* wu = (const float*)d_in[3];
    const float* wd = (const float*)d_in[4];
    float* out = (float*)d_out;

    static int smem_set = 0;
    if (!smem_set) {
        cudaFuncSetAttribute(gateup_mma, cudaFuncAttributeMaxDynamicSharedMemorySize, GU_SMEM);
        cudaFuncSetAttribute(down_mma,   cudaFuncAttributeMaxDynamicSharedMemorySize, DN_SMEM);
        smem_set = 1;
    }

    cudaMemsetAsync(out, 0, (size_t)T_TOK * HDIM * sizeof(float));
    zero_counts_kernel<<<1, 64>>>();
    xcvt_kernel<<<T_TOK * HDIM / 2048, 256>>>(x);
    router_kernel<<<T_TOK / 16, 256>>>(x, gw);

    dim3 gu_grid(IDIM / 64, T_TOK / 128, NEXP);
    gateup_mma<<<gu_grid, 384, GU_SMEM>>>(wg, wu);

    dim3 dn_grid(HDIM / 128, T_TOK / 128, NEXP);
    down_mma<<<dn_grid, 384, DN_SMEM>>>(wd, out);
}

// round 9
// speedup vs baseline: 2.3756x; 2.3756x over previous
#include <cuda_runtime.h>
#include <cuda_fp16.h>
#include <math.h>
#include <stdint.h>

#define T_TOK 1024
#define HDIM  2048
#define NEXP  64
#define IDIM  768
#define TOPK  8

// ---------------- device scratch ----------------
__device__ int    g_count[NEXP];
__device__ int    g_entry[NEXP * T_TOK];           // token*8 + slot
__device__ float  g_wt   [NEXP * T_TOK];
__device__ __half g_act  [T_TOK * TOPK * IDIM];    // fp16 silu(g)*u*w, gathered
__device__ __half g_x16  [T_TOK * HDIM];           // fp16 copy of hidden_states

// ---------------- helpers ----------------
__device__ __forceinline__ uint32_t smem_u32(const void* p) {
    uint32_t a;
    asm("{ .reg .u64 t; cvta.to.shared.u64 t, %1; cvt.u32.u64 %0, t; }" : "=r"(a) : "l"(p));
    return a;
}
__device__ __forceinline__ void sts128(uint32_t a, uint32_t x, uint32_t y, uint32_t z, uint32_t w) {
    asm volatile("st.shared.v4.b32 [%0], {%1,%2,%3,%4};" :: "r"(a), "r"(x), "r"(y), "r"(z), "r"(w));
}
__device__ __forceinline__ void ldsm4(uint32_t& r0, uint32_t& r1, uint32_t& r2, uint32_t& r3, uint32_t a) {
    asm volatile("ldmatrix.sync.aligned.m8n8.x4.shared.b16 {%0,%1,%2,%3}, [%4];"
                 : "=r"(r0), "=r"(r1), "=r"(r2), "=r"(r3) : "r"(a));
}
__device__ __forceinline__ void ldsm4t(uint32_t& r0, uint32_t& r1, uint32_t& r2, uint32_t& r3, uint32_t a) {
    asm volatile("ldmatrix.sync.aligned.m8n8.x4.trans.shared.b16 {%0,%1,%2,%3}, [%4];"
                 : "=r"(r0), "=r"(r1), "=r"(r2), "=r"(r3) : "r"(a));
}
__device__ __forceinline__ void mma_h(float& c0, float& c1, float& c2, float& c3,
                                      uint32_t a0, uint32_t a1, uint32_t a2, uint32_t a3,
                                      uint32_t b0, uint32_t b1) {
    asm volatile("mma.sync.aligned.m16n8k16.row.col.f32.f16.f16.f32 "
                 "{%0,%1,%2,%3},{%4,%5,%6,%7},{%8,%9},{%0,%1,%2,%3};"
                 : "+f"(c0), "+f"(c1), "+f"(c2), "+f"(c3)
                 : "r"(a0), "r"(a1), "r"(a2), "r"(a3), "r"(b0), "r"(b1));
}
__device__ __forceinline__ void cvt2h(float4 f, uint32_t& h0, uint32_t& h1) {
    __half2 a = __floats2half2_rn(f.x, f.y);
    __half2 b = __floats2half2_rn(f.z, f.w);
    h0 = *(uint32_t*)&a; h1 = *(uint32_t*)&b;
}
// async copy: 16B global->shared, src-size 0 => zero-fill
__device__ __forceinline__ void cpa16(uint32_t saddr, const void* gaddr, uint32_t srcsz) {
    asm volatile("cp.async.cg.shared.global [%0], [%1], 16, %2;"
                 :: "r"(saddr), "l"(gaddr), "r"(srcsz) : "memory");
}
#define CP_COMMIT() asm volatile("cp.async.commit_group;" ::: "memory")
#define CP_WAIT0()  asm volatile("cp.async.wait_group 0;" ::: "memory")

// smem geometry (fp16 elems):
//   A tile 128x32, row stride 40 elems (80B, ldsm conflict-free)
//   B64 tile 32x64,  row stride 72 elems (144B, conflict-free)
//   B128 tile 32x128, row stride 136 elems (272B, conflict-free)
#define A_BYTES    10240   // 128*40*2
#define B1_BYTES   4608    // 32*72*2
#define B128_BYTES 8704    // 32*272

// ---------------- kernel 0: reset counters ----------------
__global__ void zero_counts_kernel() {
    if (threadIdx.x < NEXP) g_count[threadIdx.x] = 0;
}

// ---------------- kernel 0b: x -> fp16 ----------------
__global__ __launch_bounds__(256)
void xcvt_kernel(const float* __restrict__ x) {
    int i = (blockIdx.x * 256 + threadIdx.x) * 8;
    float4 f0 = *(const float4*)(x + i);
    float4 f1 = *(const float4*)(x + i + 4);
    uint4 v;
    cvt2h(f0, v.x, v.y);
    cvt2h(f1, v.z, v.w);
    *(uint4*)(g_x16 + i) = v;
}

// ---------------- kernel 1: router GEMM + top-8 + bucket scatter ----------------
__global__ __launch_bounds__(256)
void router_kernel(const float* __restrict__ x, const float* __restrict__ gw) {
    __shared__ float As[16][17];
    __shared__ float Bs[16][68];
    __shared__ float Ls[16][68];

    const int t0  = blockIdx.x * 16;
    const int tid = threadIdx.x;
    const int tx  = tid & 15;
    const int ty  = tid >> 4;

    const int am = tid >> 4, ak = tid & 15;
    const int be = tid & 63, bk4 = (tid >> 6) * 4;

    float acc[4] = {0.f, 0.f, 0.f, 0.f};

    for (int k0 = 0; k0 < HDIM; k0 += 16) {
        As[ak][am] = x[(size_t)(t0 + am) * HDIM + k0 + ak];
        float4 bv = *(const float4*)(gw + (size_t)be * HDIM + k0 + bk4);
        Bs[bk4 + 0][be] = bv.x; Bs[bk4 + 1][be] = bv.y;
        Bs[bk4 + 2][be] = bv.z; Bs[bk4 + 3][be] = bv.w;
        __syncthreads();
#pragma unroll
        for (int kk = 0; kk < 16; kk++) {
            float a = As[kk][ty];
#pragma unroll
            for (int j = 0; j < 4; j++) acc[j] += a * Bs[kk][tx * 4 + j];
        }
        __syncthreads();
    }

#pragma unroll
    for (int j = 0; j < 4; j++) Ls[ty][tx * 4 + j] = acc[j];
    __syncthreads();

    if (tid < 16) {
        int   sel[TOPK];
        float sv [TOPK];
        unsigned long long mask = 0ull;
#pragma unroll
        for (int k = 0; k < TOPK; k++) {
            float best = -1e30f;
            int   be_  = 0;
            for (int e = 0; e < NEXP; e++) {
                if ((mask >> e) & 1ull) continue;
                float v = Ls[tid][e];
                if (v > best) { best = v; be_ = e; }
            }
            mask |= (1ull << be_);
            sel[k] = be_;
            sv[k]  = best;
        }
        float mx = sv[0];
        float s  = 0.f;
#pragma unroll
        for (int k = 0; k < TOPK; k++) { sv[k] = expf(sv[k] - mx); s += sv[k]; }
        float inv = 1.f / s;
#pragma unroll
        for (int k = 0; k < TOPK; k++) {
            int e   = sel[k];
            int pos = atomicAdd(&g_count[e], 1);
            g_entry[e * T_TOK + pos] = (t0 + tid) * TOPK + k;
            g_wt   [e * T_TOK + pos] = sv[k] * inv;
        }
    }
}

// ---------------- kernel 2: gate+up HMMA GEMM, fused SwiGLU ----------------
// BM=128 gathered tokens, BN=64 (both gate & up), BK=32.
// A via cp.async from fp16 g_x16; B fp32->fp16 in regs.
#define GU_BUF  (A_BYTES + 2 * B1_BYTES)             // 19456
#define GU_SMEM (1024 + 2 * GU_BUF)                  // 39936

__global__ __launch_bounds__(256, 2)
void gateup_mma(const float* __restrict__ wg,
                const float* __restrict__ wu) {
    extern __shared__ char smem[];
    const int e   = blockIdx.z;
    const int cnt = g_count[e];
    const int m0  = blockIdx.y * 128;
    if (m0 >= cnt) return;
    const int n0  = blockIdx.x * 64;
    const int tid  = threadIdx.x;
    const int wid  = tid >> 5;
    const int lane = tid & 31;

    const uint32_t sb = smem_u32(smem);
    int*   sEnt = (int*)smem;
    float* sW   = (float*)(smem + 512);

    if (tid < 128) {
        int mi = m0 + tid;
        if (mi < cnt) { sEnt[tid] = g_entry[e * T_TOK + mi]; sW[tid] = g_wt[e * T_TOK + mi]; }
        else          { sEnt[tid] = -1;                      sW[tid] = 0.f; }
    }
    __syncthreads();

    const int wm = wid >> 1, wn = wid & 1;
    const bool strip_active = (m0 + wm * 32) < cnt;

    // A loader: 2 threads/row, 32B each, cp.async from g_x16
    const int arow = tid >> 1;
    const int aent = sEnt[arow];
    const __half* axg = g_x16 + (size_t)(aent >= 0 ? (aent >> 3) : 0) * HDIM + (tid & 1) * 16;
    const uint32_t aSrcSz = (aent >= 0) ? 16u : 0u;
    const uint32_t aoff = (uint32_t)(arow * 80 + (tid & 1) * 32);

    // B loader
    const int brow = tid >> 3, bcol = (tid & 7) * 8;
    const float* pg = wg + (size_t)e * HDIM * IDIM + n0 + bcol;
    const float* pu = wu + (size_t)e * HDIM * IDIM + n0 + bcol;

    float4 fG[2], fU[2];
    auto cpaA = [&](int k0, int b) {
        const uint32_t base = sb + 1024 + b * GU_BUF + aoff;
        const __half* src = axg + k0;
        cpa16(base,      src,     aSrcSz);
        cpa16(base + 16, src + 8, aSrcSz);
    };
    auto loadB = [&](int k0) {
        const float* gp = pg + (size_t)(k0 + brow) * IDIM;
        const float* up = pu + (size_t)(k0 + brow) * IDIM;
        fG[0] = *(const float4*)gp; fG[1] = *(const float4*)(gp + 4);
        fU[0] = *(const float4*)up; fU[1] = *(const float4*)(up + 4);
    };
    auto stsB = [&](int b) {
        const uint32_t base = sb + 1024 + b * GU_BUF;
        const uint32_t Bg = base + A_BYTES, Bu = Bg + B1_BYTES;
        uint32_t h0, h1, h2, h3;
        const uint32_t offB = brow * 144 + bcol * 2;
        cvt2h(fG[0], h0, h1); cvt2h(fG[1], h2, h3);
        sts128(Bg + offB, h0, h1, h2, h3);
        cvt2h(fU[0], h0, h1); cvt2h(fU[1], h2, h3);
        sts128(Bu + offB, h0, h1, h2, h3);
    };

    float accg[2][4][4], accu[2][4][4];
#pragma unroll
    for (int i = 0; i < 2; i++)
#pragma unroll
        for (int j = 0; j < 4; j++)
#pragma unroll
            for (int q = 0; q < 4; q++) { accg[i][j][q] = 0.f; accu[i][j][q] = 0.f; }

    auto compute = [&](int b) {
        const uint32_t base = sb + 1024 + b * GU_BUF;
        const uint32_t Ah = base;
        const uint32_t Bg = base + A_BYTES, Bu = Bg + B1_BYTES;
#pragma unroll
        for (int kk = 0; kk < 2; kk++) {
            uint32_t ah[2][4];
            const uint32_t acol = (kk * 16 + (lane >> 4) * 8) * 2;
#pragma unroll
            for (int i = 0; i < 2; i++) {
                uint32_t ra = (wm * 32 + i * 16 + (lane & 15)) * 80 + acol;
                ldsm4(ah[i][0], ah[i][1], ah[i][2], ah[i][3], Ah + ra);
            }
            const uint32_t brow_ = kk * 16 + ((lane >> 3) & 1) * 8 + (lane & 7);
#pragma unroll
            for (int hf = 0; hf < 2; hf++) {
                const uint32_t rb = brow_ * 144 + (wn * 32 + hf * 16 + (lane >> 4) * 8) * 2;
                uint32_t g0, g1, g2, g3;
                ldsm4t(g0, g1, g2, g3, Bg + rb);
#pragma unroll
                for (int i = 0; i < 2; i++) {
                    float* c0 = accg[i][hf * 2 + 0];
                    float* c1 = accg[i][hf * 2 + 1];
                    mma_h(c0[0], c0[1], c0[2], c0[3], ah[i][0], ah[i][1], ah[i][2], ah[i][3], g0, g1);
                    mma_h(c1[0], c1[1], c1[2], c1[3], ah[i][0], ah[i][1], ah[i][2], ah[i][3], g2, g3);
                }
                uint32_t u0, u1, u2, u3;
                ldsm4t(u0, u1, u2, u3, Bu + rb);
#pragma unroll
                for (int i = 0; i < 2; i++) {
                    float* c0 = accu[i][hf * 2 + 0];
                    float* c1 = accu[i][hf * 2 + 1];
                    mma_h(c0[0], c0[1], c0[2], c0[3], ah[i][0], ah[i][1], ah[i][2], ah[i][3], u0, u1);
                    mma_h(c1[0], c1[1], c1[2], c1[3], ah[i][0], ah[i][1], ah[i][2], ah[i][3], u2, u3);
                }
            }
        }
    };

    cpaA(0, 0);
    CP_COMMIT();
    loadB(0);
    stsB(0);
    CP_WAIT0();
    __syncthreads();

    const int C = HDIM / 32;
    for (int c = 0; c < C; c++) {
        if (c + 1 < C) {
            cpaA((c + 1) * 32, (c + 1) & 1);
            CP_COMMIT();
            loadB((c + 1) * 32);
        }
        if (strip_active) compute(c & 1);
        if (c + 1 < C) {
            stsB((c + 1) & 1);
            CP_WAIT0();
            __syncthreads();
        }
    }

    // epilogue: silu(g)*u*w -> fp16 plane
    if (strip_active) {
#pragma unroll
        for (int i = 0; i < 2; i++)
#pragma unroll
            for (int nt = 0; nt < 4; nt++) {
                const int r    = wm * 32 + i * 16 + (lane >> 2);
                const int cof  = n0 + wn * 32 + nt * 8 + (lane & 3) * 2;
#pragma unroll
                for (int half_ = 0; half_ < 2; half_++) {
                    const int rr  = r + half_ * 8;
                    const int ent = sEnt[rr];
                    if (ent >= 0) {
                        const float w = sW[rr];
                        float g0 = accg[i][nt][half_ * 2 + 0], g1 = accg[i][nt][half_ * 2 + 1];
                        float u0 = accu[i][nt][half_ * 2 + 0], u1 = accu[i][nt][half_ * 2 + 1];
                        float v0 = g0 / (1.f + expf(-g0)) * u0 * w;
                        float v1 = g1 / (1.f + expf(-g1)) * u1 * w;
                        *(__half2*)(g_act + (size_t)ent * IDIM + cof) =
                            __floats2half2_rn(v0, v1);
                    }
                }
            }
    }
}

// ---------------- kernel 3: down HMMA GEMM, BN=128, atomic scatter ----------------
#define DN_BUF  (A_BYTES + B128_BYTES)               // 18944
#define DN_SMEM (1024 + 2 * DN_BUF)                  // 38912

__global__ __launch_bounds__(256, 2)
void down_mma(const float* __restrict__ wd, float* __restrict__ out) {
    extern __shared__ char smem[];
    const int e   = blockIdx.z;
    const int cnt = g_count[e];
    const int m0  = blockIdx.y * 128;
    if (m0 >= cnt) return;
    const int n0  = blockIdx.x * 128;
    const int tid  = threadIdx.x;
    const int wid  = tid >> 5;
    const int lane = tid & 31;

    const uint32_t sb = smem_u32(smem);
    int* sEnt = (int*)smem;

    if (tid < 128) {
        int mi = m0 + tid;
        sEnt[tid] = (mi < cnt) ? g_entry[e * T_TOK + mi] : -1;
    }
    __syncthreads();

    const int wm = wid >> 1, wn = wid & 1;
    const bool strip_active = (m0 + wm * 32) < cnt;

    // A loader: cp.async from fp16 g_act
    const int arow = tid >> 1;
    const int aent = sEnt[arow];
    const __half* axg = g_act + (size_t)(aent >= 0 ? aent : 0) * IDIM + (tid & 1) * 16;
    const uint32_t aSrcSz = (aent >= 0) ? 16u : 0u;
    const uint32_t aoff = (uint32_t)(arow * 80 + (tid & 1) * 32);

    // B loader: 32 rows x 128 cols fp32; two 8-col segments per thread
    const int brow = tid >> 3, c8 = (tid & 7) * 8;
    const float* pb = wd + (size_t)e * IDIM * HDIM + n0 + c8;

    float4 fB[4];
    auto cpaA = [&](int k0, int b) {
        const uint32_t base = sb + 1024 + b * DN_BUF + aoff;
        const __half* src = axg + k0;
        cpa16(base,      src,     aSrcSz);
        cpa16(base + 16, src + 8, aSrcSz);
    };
    auto loadB = [&](int k0) {
        const float* bp = pb + (size_t)(k0 + brow) * HDIM;
        fB[0] = *(const float4*)bp;        fB[1] = *(const float4*)(bp + 4);
        fB[2] = *(const float4*)(bp + 64); fB[3] = *(const float4*)(bp + 68);
    };
    auto stsB = [&](int b) {
        const uint32_t base = sb + 1024 + b * DN_BUF;
        const uint32_t Bh = base + A_BYTES;
        uint32_t h0, h1, h2, h3;
        const uint32_t offB = brow * 272 + c8 * 2;
        cvt2h(fB[0], h0, h1); cvt2h(fB[1], h2, h3);
        sts128(Bh + offB, h0, h1, h2, h3);
        cvt2h(fB[2], h0, h1); cvt2h(fB[3], h2, h3);
        sts128(Bh + offB + 128, h0, h1, h2, h3);
    };

    float acc[2][8][4];
#pragma unroll
    for (int i = 0; i < 2; i++)
#pragma unroll
        for (int j = 0; j < 8; j++)
#pragma unroll
            for (int q = 0; q < 4; q++) acc[i][j][q] = 0.f;

    auto compute = [&](int b) {
        const uint32_t base = sb + 1024 + b * DN_BUF;
        const uint32_t Ah = base;
        const uint32_t Bh = base + A_BYTES;
#pragma unroll
        for (int kk = 0; kk < 2; kk++) {
            uint32_t ah[2][4];
            const uint32_t acol = (kk * 16 + (lane >> 4) * 8) * 2;
#pragma unroll
            for (int i = 0; i < 2; i++) {
                uint32_t ra = (wm * 32 + i * 16 + (lane & 15)) * 80 + acol;
                ldsm4(ah[i][0], ah[i][1], ah[i][2], ah[i][3], Ah + ra);
            }
            const uint32_t brow_ = kk * 16 + ((lane >> 3) & 1) * 8 + (lane & 7);
#pragma unroll
            for (int hf = 0; hf < 4; hf++) {
                const uint32_t rb = brow_ * 272 + (wn * 64 + hf * 16 + (lane >> 4) * 8) * 2;
                uint32_t b0, b1, b2, b3;
                ldsm4t(b0, b1, b2, b3, Bh + rb);
#pragma unroll
                for (int i = 0; i < 2; i++) {
                    float* c0 = acc[i][hf * 2 + 0];
                    float* c1 = acc[i][hf * 2 + 1];
                    mma_h(c0[0], c0[1], c0[2], c0[3], ah[i][0], ah[i][1], ah[i][2], ah[i][3], b0, b1);
                    mma_h(c1[0], c1[1], c1[2], c1[3], ah[i][0], ah[i][1], ah[i][2], ah[i][3], b2, b3);
                }
            }
        }
    };

    cpaA(0, 0);
    CP_COMMIT();
    loadB(0);
    stsB(0);
    CP_WAIT0();
    __syncthreads();

    const int C = IDIM / 32;
    for (int c = 0; c < C; c++) {
        if (c + 1 < C) {
            cpaA((c + 1) * 32, (c + 1) & 1);
            CP_COMMIT();
            loadB((c + 1) * 32);
        }
        if (strip_active) compute(c & 1);
        if (c + 1 < C) {
            stsB((c + 1) & 1);
            CP_WAIT0();
            __syncthreads();
        }
    }

    if (strip_active) {
#pragma unroll
        for (int i = 0; i < 2; i++)
#pragma unroll
            for (int nt = 0; nt < 8; nt++) {
                const int r   = wm * 32 + i * 16 + (lane >> 2);
                const int cof = n0 + wn * 64 + nt * 8 + (lane & 3) * 2;
#pragma unroll
                for (int half_ = 0; half_ < 2; half_++) {
                    const int rr  = r + half_ * 8;
                    const int ent = sEnt[rr];
                    if (ent >= 0) {
                        float* dst = out + (size_t)(ent >> 3) * HDIM + cof;
                        atomicAdd(dst,     acc[i][nt][half_ * 2 + 0]);
                        atomicAdd(dst + 1, acc[i][nt][half_ * 2 + 1]);
                    }
                }
            }
    }
}

// ---------------- launch ----------------
extern "C" void kernel_launch(void* const* d_in, const int* in_sizes, int n_in,
                              void* d_out, int out_size) {
    const float* x  = (const float*)d_in[0];
    const float* gw = (const float*)d_in[1];
    const float* wg = (const float*)d_in[2];
    const float* wu = (const float*)d_in[3];
    const float* wd = (const float*)d_in[4];
    float* out = (float*)d_out;

    static int smem_set = 0;
    if (!smem_set) {
        cudaFuncSetAttribute(gateup_mma, cudaFuncAttributeMaxDynamicSharedMemorySize, GU_SMEM);
        cudaFuncSetAttribute(down_mma,   cudaFuncAttributeMaxDynamicSharedMemorySize, DN_SMEM);
        smem_set = 1;
    }

    cudaMemsetAsync(out, 0, (size_t)T_TOK * HDIM * sizeof(float));
    zero_counts_kernel<<<1, 64>>>();
    xcvt_kernel<<<T_TOK * HDIM / 2048, 256>>>(x);
    router_kernel<<<T_TOK / 16, 256>>>(x, gw);

    dim3 gu_grid(IDIM / 64, T_TOK / 128, NEXP);
    gateup_mma<<<gu_grid, 256, GU_SMEM>>>(wg, wu);

    dim3 dn_grid(HDIM / 128, T_TOK / 128, NEXP);
    down_mma<<<dn_grid, 256, DN_SMEM>>>(wd, out);
}